// round 1
// baseline (speedup 1.0000x reference)
#include <cuda_runtime.h>
#include <math.h>

// Problem shapes (fixed for this dataset entry)
#define B_   4
#define S_   4096
#define D_   1024
#define E_   8
#define M_   (B_ * S_)       // 16384 rows of the main GEMM
#define NCH  16              // pooling s-chunks

// ---------------- scratch (allocation-free: __device__ globals) ----------------
__device__ float g_part[NCH][B_][D_];     // partial pooling sums
__device__ float g_pooled[B_][D_];        // mean-pooled inputs  [B, D]
__device__ float g_w[E_];                 // batch-averaged routing probs [E]
__device__ float g_merged_w[D_ * D_];     // merged expert weight [o][d] (row-major, K contiguous)
__device__ float g_merged_b[D_];          // merged bias

// ---------------- Kernel 1a: partial pooling sums (deterministic, no atomics) --
// grid (D_/256, B_, NCH), block 256
__global__ void pool_partial_kernel(const float* __restrict__ x) {
    const int d = blockIdx.x * blockDim.x + threadIdx.x;
    const int b = blockIdx.y;
    const int c = blockIdx.z;
    const int s0 = c * (S_ / NCH);
    const float* p = x + (size_t)b * S_ * D_ + (size_t)s0 * D_ + d;
    float acc = 0.f;
#pragma unroll 8
    for (int i = 0; i < S_ / NCH; ++i) {
        acc += p[(size_t)i * D_];
    }
    g_part[c][b][d] = acc;
}

// ---------------- Kernel 1b: finish pooling --------------------------------
// grid (D_/256, B_), block 256
__global__ void pool_final_kernel() {
    const int d = blockIdx.x * blockDim.x + threadIdx.x;
    const int b = blockIdx.y;
    float acc = 0.f;
#pragma unroll
    for (int c = 0; c < NCH; ++c) acc += g_part[c][b][d];
    g_pooled[b][d] = acc * (1.0f / S_);
}

// ---------------- Kernel 2: router (logits -> softmax -> mean over B) ------
// one block, 1024 threads (32 warps = B_*E_ pairs)
__global__ void router_kernel(const float* __restrict__ rw,
                              const float* __restrict__ rb) {
    __shared__ float logits[B_][E_];
    const int warp = threadIdx.x >> 5;
    const int lane = threadIdx.x & 31;
    const int b = warp / E_;
    const int e = warp % E_;

    float s = 0.f;
    for (int d = lane; d < D_; d += 32)
        s += g_pooled[b][d] * rw[e * D_ + d];
#pragma unroll
    for (int o = 16; o > 0; o >>= 1) s += __shfl_xor_sync(0xFFFFFFFFu, s, o);
    if (lane == 0) logits[b][e] = s + rb[e];
    __syncthreads();

    if (threadIdx.x < E_) {
        const int ee = threadIdx.x;
        float acc = 0.f;
#pragma unroll
        for (int bb = 0; bb < B_; ++bb) {
            float mx = -1e30f;
#pragma unroll
            for (int j = 0; j < E_; ++j) mx = fmaxf(mx, logits[bb][j]);
            float den = 0.f;
#pragma unroll
            for (int j = 0; j < E_; ++j) den += expf(logits[bb][j] - mx);
            acc += expf(logits[bb][ee] - mx) / den;
        }
        g_w[ee] = acc * (1.0f / B_);
    }
}

// ---------------- Kernel 3: merge expert weights + bias --------------------
// grid (D_*D_/4/256), block 256; vectorized float4
__global__ void merge_kernel(const float* __restrict__ ew,
                             const float* __restrict__ eb) {
    __shared__ float ws[E_];
    if (threadIdx.x < E_) ws[threadIdx.x] = g_w[threadIdx.x];
    __syncthreads();

    const int idx = blockIdx.x * blockDim.x + threadIdx.x;  // float4 index
    float4 acc = make_float4(0.f, 0.f, 0.f, 0.f);
#pragma unroll
    for (int e = 0; e < E_; ++e) {
        const float we = ws[e];
        float4 v = reinterpret_cast<const float4*>(ew)[(size_t)e * (D_ * D_ / 4) + idx];
        acc.x += we * v.x;  acc.y += we * v.y;
        acc.z += we * v.z;  acc.w += we * v.w;
    }
    reinterpret_cast<float4*>(g_merged_w)[idx] = acc;

    if (blockIdx.x == 0 && idx < D_ / 4) {
        float4 bacc = make_float4(0.f, 0.f, 0.f, 0.f);
#pragma unroll
        for (int e = 0; e < E_; ++e) {
            const float we = ws[e];
            float4 v = reinterpret_cast<const float4*>(eb)[e * (D_ / 4) + idx];
            bacc.x += we * v.x;  bacc.y += we * v.y;
            bacc.z += we * v.z;  bacc.w += we * v.w;
        }
        reinterpret_cast<float4*>(g_merged_b)[idx] = bacc;
    }
}

// ---------------- Kernel 4: main SGEMM  out = X @ W^T + b ------------------
// X: [M_, D_] row-major; W: g_merged_w [N=D_ rows (o), K=D_ cols] row-major.
// 128x128 tile, BK=8, 256 threads, 8x8 per thread, register prefetch.
#define BM 128
#define BN 128
#define BK 8

__global__ __launch_bounds__(256, 2)
void gemm_kernel(const float* __restrict__ A, float* __restrict__ out) {
    __shared__ float As[BK][BM];
    __shared__ float Bs[BK][BN];

    const int tid = threadIdx.x;
    const int m0 = blockIdx.y * BM;
    const int n0 = blockIdx.x * BN;
    const int tx = tid & 15;    // n-direction, 16 threads
    const int ty = tid >> 4;    // m-direction, 16 threads

    // loader mapping: one float4 per thread per tile per operand
    const int lr = tid >> 1;          // row within tile: 0..127
    const int lc = (tid & 1) * 4;     // k offset: 0 or 4

    const float* Ag = A + (size_t)(m0 + lr) * D_ + lc;
    const float* Bg = g_merged_w + (size_t)(n0 + lr) * D_ + lc;

    float4 aReg = *reinterpret_cast<const float4*>(Ag);
    float4 bReg = *reinterpret_cast<const float4*>(Bg);

    float acc[8][8];
#pragma unroll
    for (int i = 0; i < 8; ++i)
#pragma unroll
        for (int j = 0; j < 8; ++j) acc[i][j] = 0.f;

    for (int kt = 0; kt < D_; kt += BK) {
        // store current tile to shared (transposed: [k][row])
        As[lc + 0][lr] = aReg.x;  As[lc + 1][lr] = aReg.y;
        As[lc + 2][lr] = aReg.z;  As[lc + 3][lr] = aReg.w;
        Bs[lc + 0][lr] = bReg.x;  Bs[lc + 1][lr] = bReg.y;
        Bs[lc + 2][lr] = bReg.z;  Bs[lc + 3][lr] = bReg.w;
        __syncthreads();

        // prefetch next tile into registers (overlaps with compute below)
        if (kt + BK < D_) {
            aReg = *reinterpret_cast<const float4*>(Ag + kt + BK);
            bReg = *reinterpret_cast<const float4*>(Bg + kt + BK);
        }

#pragma unroll
        for (int kk = 0; kk < BK; ++kk) {
            float a[8], b[8];
            float4 t;
            t = *reinterpret_cast<const float4*>(&As[kk][ty * 4]);
            a[0] = t.x; a[1] = t.y; a[2] = t.z; a[3] = t.w;
            t = *reinterpret_cast<const float4*>(&As[kk][64 + ty * 4]);
            a[4] = t.x; a[5] = t.y; a[6] = t.z; a[7] = t.w;
            t = *reinterpret_cast<const float4*>(&Bs[kk][tx * 4]);
            b[0] = t.x; b[1] = t.y; b[2] = t.z; b[3] = t.w;
            t = *reinterpret_cast<const float4*>(&Bs[kk][64 + tx * 4]);
            b[4] = t.x; b[5] = t.y; b[6] = t.z; b[7] = t.w;
#pragma unroll
            for (int i = 0; i < 8; ++i)
#pragma unroll
                for (int j = 0; j < 8; ++j)
                    acc[i][j] += a[i] * b[j];
        }
        __syncthreads();
    }

    // epilogue: + bias, write out
    float4 bias0 = *reinterpret_cast<const float4*>(&g_merged_b[n0 + tx * 4]);
    float4 bias1 = *reinterpret_cast<const float4*>(&g_merged_b[n0 + 64 + tx * 4]);

#pragma unroll
    for (int i = 0; i < 8; ++i) {
        const int m = m0 + ((i < 4) ? (ty * 4 + i) : (64 + ty * 4 + (i - 4)));
        float* orow = out + (size_t)m * D_ + n0;
        float4 v0 = make_float4(acc[i][0] + bias0.x, acc[i][1] + bias0.y,
                                acc[i][2] + bias0.z, acc[i][3] + bias0.w);
        float4 v1 = make_float4(acc[i][4] + bias1.x, acc[i][5] + bias1.y,
                                acc[i][6] + bias1.z, acc[i][7] + bias1.w);
        *reinterpret_cast<float4*>(orow + tx * 4) = v0;
        *reinterpret_cast<float4*>(orow + 64 + tx * 4) = v1;
    }
}

// ---------------- launch ----------------------------------------------------
extern "C" void kernel_launch(void* const* d_in, const int* in_sizes, int n_in,
                              void* d_out, int out_size) {
    const float* x  = (const float*)d_in[0];   // inputs   [B, S, D]
    const float* rw = (const float*)d_in[1];   // router_w [E, D]
    const float* rb = (const float*)d_in[2];   // router_b [E]
    const float* ew = (const float*)d_in[3];   // expert_w [E, D, D]
    const float* eb = (const float*)d_in[4];   // expert_b [E, D]
    float* out = (float*)d_out;                // [B, S, D]

    (void)in_sizes; (void)n_in; (void)out_size;

    pool_partial_kernel<<<dim3(D_ / 256, B_, NCH), 256>>>(x);
    pool_final_kernel<<<dim3(D_ / 256, B_), 256>>>();
    router_kernel<<<1, 1024>>>(rw, rb);
    merge_kernel<<<(D_ * D_ / 4) / 256, 256>>>(ew, eb);
    gemm_kernel<<<dim3(D_ / BN, M_ / BM), 256>>>(x, out);
}

// round 3
// speedup vs baseline: 2.1519x; 2.1519x over previous
#include <cuda_runtime.h>
#include <cuda_bf16.h>
#include <math.h>
#include <stdint.h>

// Problem shapes (fixed)
#define B_   4
#define S_   4096
#define D_   1024
#define E_   8
#define M_   (B_ * S_)
#define NCH  16

// ---------------- scratch (__device__ globals: allocation-free) -------------
__device__ float g_part[NCH][B_][D_];
__device__ float g_pooled[B_][D_];
__device__ float g_w[E_];
__device__ float g_merged_b[D_];
__device__ __nv_bfloat16 g_whi[D_ * D_];
__device__ __nv_bfloat16 g_wlo[D_ * D_];
__device__ __nv_bfloat16 g_xhi[(size_t)M_ * D_];
__device__ __nv_bfloat16 g_xlo[(size_t)M_ * D_];

// ---------------- PTX helpers ----------------------------------------------
__device__ __forceinline__ uint32_t smem_u32(const void* p) {
    uint32_t a;
    asm("{ .reg .u64 t; cvta.to.shared.u64 t, %1; cvt.u32.u64 %0, t; }"
        : "=r"(a) : "l"(p));
    return a;
}
#define CP16(sm, gp) \
    asm volatile("cp.async.cg.shared.global [%0], [%1], 16;" :: "r"(sm), "l"(gp) : "memory")
#define CP_COMMIT() asm volatile("cp.async.commit_group;" ::: "memory")
#define CP_WAIT(n)  asm volatile("cp.async.wait_group %0;" :: "n"(n) : "memory")

#define LDSM_X4(r0, r1, r2, r3, addr)                                         \
    asm volatile("ldmatrix.sync.aligned.m8n8.x4.shared.b16 {%0,%1,%2,%3}, [%4];" \
        : "=r"(r0), "=r"(r1), "=r"(r2), "=r"(r3) : "r"(addr))

#define MMA16816(d, a, b)                                                     \
    asm volatile("mma.sync.aligned.m16n8k16.row.col.f32.bf16.bf16.f32 "       \
        "{%0,%1,%2,%3}, {%4,%5,%6,%7}, {%8,%9}, {%0,%1,%2,%3};"               \
        : "+f"((d)[0]), "+f"((d)[1]), "+f"((d)[2]), "+f"((d)[3])              \
        : "r"((a)[0]), "r"((a)[1]), "r"((a)[2]), "r"((a)[3]),                 \
          "r"((b)[0]), "r"((b)[1]))

// ---------------- Kernel 1a/1b: pooling ------------------------------------
__global__ void pool_partial_kernel(const float* __restrict__ x) {
    const int d = blockIdx.x * blockDim.x + threadIdx.x;
    const int b = blockIdx.y, c = blockIdx.z;
    const float* p = x + (size_t)b * S_ * D_ + (size_t)c * (S_ / NCH) * D_ + d;
    float acc = 0.f;
#pragma unroll 8
    for (int i = 0; i < S_ / NCH; ++i) acc += p[(size_t)i * D_];
    g_part[c][b][d] = acc;
}
__global__ void pool_final_kernel() {
    const int d = blockIdx.x * blockDim.x + threadIdx.x;
    const int b = blockIdx.y;
    float acc = 0.f;
#pragma unroll
    for (int c = 0; c < NCH; ++c) acc += g_part[c][b][d];
    g_pooled[b][d] = acc * (1.0f / S_);
}

// ---------------- Kernel 2: router ------------------------------------------
__global__ void router_kernel(const float* __restrict__ rw,
                              const float* __restrict__ rb) {
    __shared__ float logits[B_][E_];
    const int warp = threadIdx.x >> 5, lane = threadIdx.x & 31;
    const int b = warp / E_, e = warp % E_;
    float s = 0.f;
    for (int d = lane; d < D_; d += 32) s += g_pooled[b][d] * rw[e * D_ + d];
#pragma unroll
    for (int o = 16; o > 0; o >>= 1) s += __shfl_xor_sync(0xFFFFFFFFu, s, o);
    if (lane == 0) logits[b][e] = s + rb[e];
    __syncthreads();
    if (threadIdx.x < E_) {
        const int ee = threadIdx.x;
        float acc = 0.f;
#pragma unroll
        for (int bb = 0; bb < B_; ++bb) {
            float mx = -1e30f;
#pragma unroll
            for (int j = 0; j < E_; ++j) mx = fmaxf(mx, logits[bb][j]);
            float den = 0.f;
#pragma unroll
            for (int j = 0; j < E_; ++j) den += expf(logits[bb][j] - mx);
            acc += expf(logits[bb][ee] - mx) / den;
        }
        g_w[ee] = acc * (1.0f / B_);
    }
}

// ---------------- Kernel 3: merge -> bf16 hi/lo -----------------------------
__global__ void merge_kernel(const float* __restrict__ ew,
                             const float* __restrict__ eb) {
    __shared__ float ws[E_];
    if (threadIdx.x < E_) ws[threadIdx.x] = g_w[threadIdx.x];
    __syncthreads();
    const int idx = blockIdx.x * blockDim.x + threadIdx.x;  // float4 index
    float4 acc = make_float4(0.f, 0.f, 0.f, 0.f);
#pragma unroll
    for (int e = 0; e < E_; ++e) {
        const float we = ws[e];
        float4 v = reinterpret_cast<const float4*>(ew)[(size_t)e * (D_ * D_ / 4) + idx];
        acc.x += we * v.x; acc.y += we * v.y; acc.z += we * v.z; acc.w += we * v.w;
    }
    __nv_bfloat16 h0 = __float2bfloat16(acc.x), h1 = __float2bfloat16(acc.y);
    __nv_bfloat16 h2 = __float2bfloat16(acc.z), h3 = __float2bfloat16(acc.w);
    __nv_bfloat162* hp = reinterpret_cast<__nv_bfloat162*>(g_whi);
    __nv_bfloat162* lp = reinterpret_cast<__nv_bfloat162*>(g_wlo);
    hp[idx * 2]     = __nv_bfloat162(h0, h1);
    hp[idx * 2 + 1] = __nv_bfloat162(h2, h3);
    lp[idx * 2]     = __nv_bfloat162(__float2bfloat16(acc.x - __bfloat162float(h0)),
                                     __float2bfloat16(acc.y - __bfloat162float(h1)));
    lp[idx * 2 + 1] = __nv_bfloat162(__float2bfloat16(acc.z - __bfloat162float(h2)),
                                     __float2bfloat16(acc.w - __bfloat162float(h3)));
    if (blockIdx.x == 0 && idx < D_ / 4) {
        float4 bacc = make_float4(0.f, 0.f, 0.f, 0.f);
#pragma unroll
        for (int e = 0; e < E_; ++e) {
            const float we = ws[e];
            float4 v = reinterpret_cast<const float4*>(eb)[e * (D_ / 4) + idx];
            bacc.x += we * v.x; bacc.y += we * v.y;
            bacc.z += we * v.z; bacc.w += we * v.w;
        }
        reinterpret_cast<float4*>(g_merged_b)[idx] = bacc;
    }
}

// ---------------- Kernel 4: split X into bf16 hi/lo -------------------------
__global__ void split_x_kernel(const float* __restrict__ x) {
    const size_t i = (size_t)blockIdx.x * blockDim.x + threadIdx.x;  // float4 index
    float4 v = reinterpret_cast<const float4*>(x)[i];
    __nv_bfloat16 h0 = __float2bfloat16(v.x), h1 = __float2bfloat16(v.y);
    __nv_bfloat16 h2 = __float2bfloat16(v.z), h3 = __float2bfloat16(v.w);
    __nv_bfloat162* hp = reinterpret_cast<__nv_bfloat162*>(g_xhi);
    __nv_bfloat162* lp = reinterpret_cast<__nv_bfloat162*>(g_xlo);
    hp[i * 2]     = __nv_bfloat162(h0, h1);
    hp[i * 2 + 1] = __nv_bfloat162(h2, h3);
    lp[i * 2]     = __nv_bfloat162(__float2bfloat16(v.x - __bfloat162float(h0)),
                                   __float2bfloat16(v.y - __bfloat162float(h1)));
    lp[i * 2 + 1] = __nv_bfloat162(__float2bfloat16(v.z - __bfloat162float(h2)),
                                   __float2bfloat16(v.w - __bfloat162float(h3)));
}

// ---------------- Kernel 5: HMMA GEMM ---------------------------------------
// out[M,N] = Xhi@Whi^T + Xhi@Wlo^T + Xlo@Whi^T + bias
// A (X) and B (W) both [row][K] K-contiguous bf16.
#define BM      128
#define BN      128
#define BK      64                 // 64 bf16 = 128 bytes per row (SW128-friendly)
#define NCHK    (D_ / BK)          // 16
#define STAGES  3
#define T_BYTES (BM * 128)         // one 128x64 bf16 tile = 16 KB
#define OFF_AH  0
#define OFF_AL  (1 * T_BYTES)
#define OFF_BH  (2 * T_BYTES)
#define OFF_BL  (3 * T_BYTES)
#define STAGE_BYTES (4 * T_BYTES)  // 64 KB
#define SMEM_TOTAL  (STAGES * STAGE_BYTES)  // 192 KB

__device__ __forceinline__ void load_stage(uint32_t st, int tid,
                                           const char* Ah, const char* Al,
                                           const char* Bh, const char* Bl,
                                           size_t kbyte) {
#pragma unroll
    for (int i = 0; i < 4; ++i) {
        const int id = tid + i * 256;          // 0..1023 chunk id
        const int r = id >> 3, c = id & 7;     // row 0..127, 16B-chunk 0..7
        const uint32_t so = r * 128 + ((c ^ (r & 7)) * 16);
        const size_t go = (size_t)r * (D_ * 2) + kbyte + c * 16;
        CP16(st + OFF_AH + so, Ah + go);
        CP16(st + OFF_AL + so, Al + go);
        CP16(st + OFF_BH + so, Bh + go);
        CP16(st + OFF_BL + so, Bl + go);
    }
}

__global__ void __launch_bounds__(256, 1) gemm_kernel(float* __restrict__ out) {
    extern __shared__ char smem[];
    const uint32_t sb = smem_u32(smem);
    const int tid = threadIdx.x, wid = tid >> 5, lane = tid & 31;
    const int m0 = blockIdx.y * BM, n0 = blockIdx.x * BN;
    const int wm = (wid & 1) * 64;       // warp m-offset (2 warps over 128)
    const int wn = (wid >> 1) * 32;      // warp n-offset (4 warps over 128)

    const char* Ah0 = (const char*)(g_xhi + (size_t)m0 * D_);
    const char* Al0 = (const char*)(g_xlo + (size_t)m0 * D_);
    const char* Bh0 = (const char*)(g_whi + (size_t)n0 * D_);
    const char* Bl0 = (const char*)(g_wlo + (size_t)n0 * D_);

    // prologue: stages 0, 1
    load_stage(sb, tid, Ah0, Al0, Bh0, Bl0, 0);
    CP_COMMIT();
    load_stage(sb + STAGE_BYTES, tid, Ah0, Al0, Bh0, Bl0, 128);
    CP_COMMIT();

    float acc[4][4][4];
#pragma unroll
    for (int i = 0; i < 4; ++i)
#pragma unroll
        for (int j = 0; j < 4; ++j)
#pragma unroll
            for (int k = 0; k < 4; ++k) acc[i][j][k] = 0.f;

    // per-lane ldmatrix address components (row & 7 == lane & 7 always)
    const uint32_t sw = lane & 7;
    const uint32_t rowA = wm + (lane & 7) + ((lane >> 3) & 1) * 8;
    const uint32_t kA = (lane >> 4) & 1;
    const uint32_t rowB = wn + (lane & 7) + ((lane >> 4) & 1) * 8;
    const uint32_t kB = (lane >> 3) & 1;

#pragma unroll 1
    for (int c = 0; c < NCHK; ++c) {
        const uint32_t st = sb + (c % 3) * STAGE_BYTES;
        if (c == NCHK - 1) CP_WAIT(0); else CP_WAIT(1);
        __syncthreads();

#pragma unroll
        for (int ks = 0; ks < 4; ++ks) {
            uint32_t ah[4][4], al[4][4], bh[4][2], bl[4][2];
#pragma unroll
            for (int mf = 0; mf < 4; ++mf) {
                const uint32_t ao = st + (rowA + mf * 16) * 128 +
                                    (((ks * 2 + kA) ^ sw) * 16);
                LDSM_X4(ah[mf][0], ah[mf][1], ah[mf][2], ah[mf][3], ao + OFF_AH);
                LDSM_X4(al[mf][0], al[mf][1], al[mf][2], al[mf][3], ao + OFF_AL);
            }
#pragma unroll
            for (int np = 0; np < 2; ++np) {
                const uint32_t bo = st + (rowB + np * 16) * 128 +
                                    (((ks * 2 + kB) ^ sw) * 16);
                uint32_t t0, t1, t2, t3;
                LDSM_X4(t0, t1, t2, t3, bo + OFF_BH);
                bh[np * 2][0] = t0; bh[np * 2][1] = t1;
                bh[np * 2 + 1][0] = t2; bh[np * 2 + 1][1] = t3;
                LDSM_X4(t0, t1, t2, t3, bo + OFF_BL);
                bl[np * 2][0] = t0; bl[np * 2][1] = t1;
                bl[np * 2 + 1][0] = t2; bl[np * 2 + 1][1] = t3;
            }
#pragma unroll
            for (int mf = 0; mf < 4; ++mf)
#pragma unroll
                for (int nf = 0; nf < 4; ++nf) {
                    MMA16816(acc[mf][nf], ah[mf], bh[nf]);
                    MMA16816(acc[mf][nf], ah[mf], bl[nf]);
                    MMA16816(acc[mf][nf], al[mf], bh[nf]);
                }
        }
        __syncthreads();
        if (c + 2 < NCHK) {
            load_stage(sb + ((c + 2) % 3) * STAGE_BYTES, tid,
                       Ah0, Al0, Bh0, Bl0, (size_t)(c + 2) * 128);
            CP_COMMIT();
        }
    }

    // epilogue: acc layout c0,c1 -> (row = lane/4, cols = (lane%4)*2), c2,c3 -> row+8
    const int erow = lane >> 2;
    const int ecol = (lane & 3) * 2;
#pragma unroll
    for (int mf = 0; mf < 4; ++mf) {
#pragma unroll
        for (int nf = 0; nf < 4; ++nf) {
            const int r0 = m0 + wm + mf * 16 + erow;
            const int cc = n0 + wn + nf * 8 + ecol;
            const float2 bv = *reinterpret_cast<const float2*>(&g_merged_b[cc]);
            float2 v0 = make_float2(acc[mf][nf][0] + bv.x, acc[mf][nf][1] + bv.y);
            float2 v1 = make_float2(acc[mf][nf][2] + bv.x, acc[mf][nf][3] + bv.y);
            *reinterpret_cast<float2*>(out + (size_t)r0 * D_ + cc) = v0;
            *reinterpret_cast<float2*>(out + (size_t)(r0 + 8) * D_ + cc) = v1;
        }
    }
}

// ---------------- launch ----------------------------------------------------
extern "C" void kernel_launch(void* const* d_in, const int* in_sizes, int n_in,
                              void* d_out, int out_size) {
    const float* x  = (const float*)d_in[0];
    const float* rw = (const float*)d_in[1];
    const float* rb = (const float*)d_in[2];
    const float* ew = (const float*)d_in[3];
    const float* eb = (const float*)d_in[4];
    float* out = (float*)d_out;
    (void)in_sizes; (void)n_in; (void)out_size;

    cudaFuncSetAttribute(gemm_kernel,
                         cudaFuncAttributeMaxDynamicSharedMemorySize, SMEM_TOTAL);

    pool_partial_kernel<<<dim3(D_ / 256, B_, NCH), 256>>>(x);
    pool_final_kernel<<<dim3(D_ / 256, B_), 256>>>();
    router_kernel<<<1, 1024>>>(rw, rb);
    merge_kernel<<<(D_ * D_ / 4) / 256, 256>>>(ew, eb);
    split_x_kernel<<<(M_ * D_ / 4) / 256, 256>>>(x);
    gemm_kernel<<<dim3(D_ / BN, M_ / BM), 256, SMEM_TOTAL>>>(out);
}

// round 4
// speedup vs baseline: 2.1667x; 1.0069x over previous
#include <cuda_runtime.h>
#include <cuda_bf16.h>
#include <math.h>
#include <stdint.h>

// Problem shapes (fixed)
#define B_   4
#define S_   4096
#define D_   1024
#define E_   8
#define M_   (B_ * S_)
#define NCH  16

// ---------------- scratch (__device__ globals: allocation-free) -------------
__device__ float g_part[NCH][B_][D_];
__device__ float g_pooled[B_][D_];
__device__ float g_w[E_];
__device__ float g_merged_b[D_];
__device__ __nv_bfloat16 g_whi[D_ * D_];
__device__ __nv_bfloat16 g_wlo[D_ * D_];
__device__ __nv_bfloat16 g_xhi[(size_t)M_ * D_];
__device__ __nv_bfloat16 g_xlo[(size_t)M_ * D_];

// ---------------- PTX helpers ----------------------------------------------
__device__ __forceinline__ uint32_t smem_u32(const void* p) {
    uint32_t a;
    asm("{ .reg .u64 t; cvta.to.shared.u64 t, %1; cvt.u32.u64 %0, t; }"
        : "=r"(a) : "l"(p));
    return a;
}
#define CP16(sm, gp) \
    asm volatile("cp.async.cg.shared.global [%0], [%1], 16;" :: "r"(sm), "l"(gp) : "memory")
#define CP_COMMIT() asm volatile("cp.async.commit_group;" ::: "memory")
#define CP_WAIT(n)  asm volatile("cp.async.wait_group %0;" :: "n"(n) : "memory")

#define LDSM_X4(r0, r1, r2, r3, addr)                                         \
    asm volatile("ldmatrix.sync.aligned.m8n8.x4.shared.b16 {%0,%1,%2,%3}, [%4];" \
        : "=r"(r0), "=r"(r1), "=r"(r2), "=r"(r3) : "r"(addr))

#define MMA16816(d, a, b)                                                     \
    asm volatile("mma.sync.aligned.m16n8k16.row.col.f32.bf16.bf16.f32 "       \
        "{%0,%1,%2,%3}, {%4,%5,%6,%7}, {%8,%9}, {%0,%1,%2,%3};"               \
        : "+f"((d)[0]), "+f"((d)[1]), "+f"((d)[2]), "+f"((d)[3])              \
        : "r"((a)[0]), "r"((a)[1]), "r"((a)[2]), "r"((a)[3]),                 \
          "r"((b)[0]), "r"((b)[1]))

// ---------------- Kernel 1a/1b: pooling ------------------------------------
__global__ void pool_partial_kernel(const float* __restrict__ x) {
    const int d = blockIdx.x * blockDim.x + threadIdx.x;
    const int b = blockIdx.y, c = blockIdx.z;
    const float* p = x + (size_t)b * S_ * D_ + (size_t)c * (S_ / NCH) * D_ + d;
    float acc = 0.f;
#pragma unroll 8
    for (int i = 0; i < S_ / NCH; ++i) acc += p[(size_t)i * D_];
    g_part[c][b][d] = acc;
}
__global__ void pool_final_kernel() {
    const int d = blockIdx.x * blockDim.x + threadIdx.x;
    const int b = blockIdx.y;
    float acc = 0.f;
#pragma unroll
    for (int c = 0; c < NCH; ++c) acc += g_part[c][b][d];
    g_pooled[b][d] = acc * (1.0f / S_);
}

// ---------------- Kernel 2: router ------------------------------------------
__global__ void router_kernel(const float* __restrict__ rw,
                              const float* __restrict__ rb) {
    __shared__ float logits[B_][E_];
    const int warp = threadIdx.x >> 5, lane = threadIdx.x & 31;
    const int b = warp / E_, e = warp % E_;
    float s = 0.f;
    for (int d = lane; d < D_; d += 32) s += g_pooled[b][d] * rw[e * D_ + d];
#pragma unroll
    for (int o = 16; o > 0; o >>= 1) s += __shfl_xor_sync(0xFFFFFFFFu, s, o);
    if (lane == 0) logits[b][e] = s + rb[e];
    __syncthreads();
    if (threadIdx.x < E_) {
        const int ee = threadIdx.x;
        float acc = 0.f;
#pragma unroll
        for (int bb = 0; bb < B_; ++bb) {
            float mx = -1e30f;
#pragma unroll
            for (int j = 0; j < E_; ++j) mx = fmaxf(mx, logits[bb][j]);
            float den = 0.f;
#pragma unroll
            for (int j = 0; j < E_; ++j) den += expf(logits[bb][j] - mx);
            acc += expf(logits[bb][ee] - mx) / den;
        }
        g_w[ee] = acc * (1.0f / B_);
    }
}

// ---------------- Kernel 3: merge -> bf16 hi/lo -----------------------------
__global__ void merge_kernel(const float* __restrict__ ew,
                             const float* __restrict__ eb) {
    __shared__ float ws[E_];
    if (threadIdx.x < E_) ws[threadIdx.x] = g_w[threadIdx.x];
    __syncthreads();
    const int idx = blockIdx.x * blockDim.x + threadIdx.x;  // float4 index
    float4 acc = make_float4(0.f, 0.f, 0.f, 0.f);
#pragma unroll
    for (int e = 0; e < E_; ++e) {
        const float we = ws[e];
        float4 v = reinterpret_cast<const float4*>(ew)[(size_t)e * (D_ * D_ / 4) + idx];
        acc.x += we * v.x; acc.y += we * v.y; acc.z += we * v.z; acc.w += we * v.w;
    }
    __nv_bfloat16 h0 = __float2bfloat16(acc.x), h1 = __float2bfloat16(acc.y);
    __nv_bfloat16 h2 = __float2bfloat16(acc.z), h3 = __float2bfloat16(acc.w);
    __nv_bfloat162* hp = reinterpret_cast<__nv_bfloat162*>(g_whi);
    __nv_bfloat162* lp = reinterpret_cast<__nv_bfloat162*>(g_wlo);
    hp[idx * 2]     = __nv_bfloat162(h0, h1);
    hp[idx * 2 + 1] = __nv_bfloat162(h2, h3);
    lp[idx * 2]     = __nv_bfloat162(__float2bfloat16(acc.x - __bfloat162float(h0)),
                                     __float2bfloat16(acc.y - __bfloat162float(h1)));
    lp[idx * 2 + 1] = __nv_bfloat162(__float2bfloat16(acc.z - __bfloat162float(h2)),
                                     __float2bfloat16(acc.w - __bfloat162float(h3)));
    if (blockIdx.x == 0 && idx < D_ / 4) {
        float4 bacc = make_float4(0.f, 0.f, 0.f, 0.f);
#pragma unroll
        for (int e = 0; e < E_; ++e) {
            const float we = ws[e];
            float4 v = reinterpret_cast<const float4*>(eb)[e * (D_ / 4) + idx];
            bacc.x += we * v.x; bacc.y += we * v.y;
            bacc.z += we * v.z; bacc.w += we * v.w;
        }
        reinterpret_cast<float4*>(g_merged_b)[idx] = bacc;
    }
}

// ---------------- Kernel 4: split X into bf16 hi/lo -------------------------
__global__ void split_x_kernel(const float* __restrict__ x) {
    const size_t i = (size_t)blockIdx.x * blockDim.x + threadIdx.x;  // float4 index
    float4 v = reinterpret_cast<const float4*>(x)[i];
    __nv_bfloat16 h0 = __float2bfloat16(v.x), h1 = __float2bfloat16(v.y);
    __nv_bfloat16 h2 = __float2bfloat16(v.z), h3 = __float2bfloat16(v.w);
    __nv_bfloat162* hp = reinterpret_cast<__nv_bfloat162*>(g_xhi);
    __nv_bfloat162* lp = reinterpret_cast<__nv_bfloat162*>(g_xlo);
    hp[i * 2]     = __nv_bfloat162(h0, h1);
    hp[i * 2 + 1] = __nv_bfloat162(h2, h3);
    lp[i * 2]     = __nv_bfloat162(__float2bfloat16(v.x - __bfloat162float(h0)),
                                   __float2bfloat16(v.y - __bfloat162float(h1)));
    lp[i * 2 + 1] = __nv_bfloat162(__float2bfloat16(v.z - __bfloat162float(h2)),
                                   __float2bfloat16(v.w - __bfloat162float(h3)));
}

// ---------------- Kernel 5: HMMA GEMM ---------------------------------------
// out[M,N] = Xhi@Whi^T + Xhi@Wlo^T + Xlo@Whi^T + bias
// A (X) and B (W) both [row][K] K-contiguous bf16.
#define BM      128
#define BN      128
#define BK      64                 // 64 bf16 = 128 bytes per row (SW128-friendly)
#define NCHK    (D_ / BK)          // 16
#define STAGES  3
#define T_BYTES (BM * 128)         // one 128x64 bf16 tile = 16 KB
#define OFF_AH  0
#define OFF_AL  (1 * T_BYTES)
#define OFF_BH  (2 * T_BYTES)
#define OFF_BL  (3 * T_BYTES)
#define STAGE_BYTES (4 * T_BYTES)  // 64 KB
#define SMEM_TOTAL  (STAGES * STAGE_BYTES)  // 192 KB

__device__ __forceinline__ void load_stage(uint32_t st, int tid,
                                           const char* Ah, const char* Al,
                                           const char* Bh, const char* Bl,
                                           size_t kbyte) {
#pragma unroll
    for (int i = 0; i < 4; ++i) {
        const int id = tid + i * 256;          // 0..1023 chunk id
        const int r = id >> 3, c = id & 7;     // row 0..127, 16B-chunk 0..7
        const uint32_t so = r * 128 + ((c ^ (r & 7)) * 16);
        const size_t go = (size_t)r * (D_ * 2) + kbyte + c * 16;
        CP16(st + OFF_AH + so, Ah + go);
        CP16(st + OFF_AL + so, Al + go);
        CP16(st + OFF_BH + so, Bh + go);
        CP16(st + OFF_BL + so, Bl + go);
    }
}

__global__ void __launch_bounds__(256, 1) gemm_kernel(float* __restrict__ out) {
    extern __shared__ char smem[];
    const uint32_t sb = smem_u32(smem);
    const int tid = threadIdx.x, wid = tid >> 5, lane = tid & 31;
    const int m0 = blockIdx.y * BM, n0 = blockIdx.x * BN;
    const int wm = (wid & 1) * 64;       // warp m-offset (2 warps over 128)
    const int wn = (wid >> 1) * 32;      // warp n-offset (4 warps over 128)

    const char* Ah0 = (const char*)(g_xhi + (size_t)m0 * D_);
    const char* Al0 = (const char*)(g_xlo + (size_t)m0 * D_);
    const char* Bh0 = (const char*)(g_whi + (size_t)n0 * D_);
    const char* Bl0 = (const char*)(g_wlo + (size_t)n0 * D_);

    // prologue: stages 0, 1
    load_stage(sb, tid, Ah0, Al0, Bh0, Bl0, 0);
    CP_COMMIT();
    load_stage(sb + STAGE_BYTES, tid, Ah0, Al0, Bh0, Bl0, 128);
    CP_COMMIT();

    float acc[4][4][4];
#pragma unroll
    for (int i = 0; i < 4; ++i)
#pragma unroll
        for (int j = 0; j < 4; ++j)
#pragma unroll
            for (int k = 0; k < 4; ++k) acc[i][j][k] = 0.f;

    // per-lane ldmatrix address components (row & 7 == lane & 7 always)
    const uint32_t sw = lane & 7;
    const uint32_t rowA = wm + (lane & 7) + ((lane >> 3) & 1) * 8;
    const uint32_t kA = (lane >> 4) & 1;
    const uint32_t rowB = wn + (lane & 7) + ((lane >> 4) & 1) * 8;
    const uint32_t kB = (lane >> 3) & 1;

#pragma unroll 1
    for (int c = 0; c < NCHK; ++c) {
        const uint32_t st = sb + (c % 3) * STAGE_BYTES;
        if (c == NCHK - 1) CP_WAIT(0); else CP_WAIT(1);
        __syncthreads();

#pragma unroll
        for (int ks = 0; ks < 4; ++ks) {
            uint32_t ah[4][4], al[4][4], bh[4][2], bl[4][2];
#pragma unroll
            for (int mf = 0; mf < 4; ++mf) {
                const uint32_t ao = st + (rowA + mf * 16) * 128 +
                                    (((ks * 2 + kA) ^ sw) * 16);
                LDSM_X4(ah[mf][0], ah[mf][1], ah[mf][2], ah[mf][3], ao + OFF_AH);
                LDSM_X4(al[mf][0], al[mf][1], al[mf][2], al[mf][3], ao + OFF_AL);
            }
#pragma unroll
            for (int np = 0; np < 2; ++np) {
                const uint32_t bo = st + (rowB + np * 16) * 128 +
                                    (((ks * 2 + kB) ^ sw) * 16);
                uint32_t t0, t1, t2, t3;
                LDSM_X4(t0, t1, t2, t3, bo + OFF_BH);
                bh[np * 2][0] = t0; bh[np * 2][1] = t1;
                bh[np * 2 + 1][0] = t2; bh[np * 2 + 1][1] = t3;
                LDSM_X4(t0, t1, t2, t3, bo + OFF_BL);
                bl[np * 2][0] = t0; bl[np * 2][1] = t1;
                bl[np * 2 + 1][0] = t2; bl[np * 2 + 1][1] = t3;
            }
#pragma unroll
            for (int mf = 0; mf < 4; ++mf)
#pragma unroll
                for (int nf = 0; nf < 4; ++nf) {
                    MMA16816(acc[mf][nf], ah[mf], bh[nf]);
                    MMA16816(acc[mf][nf], ah[mf], bl[nf]);
                    MMA16816(acc[mf][nf], al[mf], bh[nf]);
                }
        }
        __syncthreads();
        if (c + 2 < NCHK) {
            load_stage(sb + ((c + 2) % 3) * STAGE_BYTES, tid,
                       Ah0, Al0, Bh0, Bl0, (size_t)(c + 2) * 128);
            CP_COMMIT();
        }
    }

    // epilogue: acc layout c0,c1 -> (row = lane/4, cols = (lane%4)*2), c2,c3 -> row+8
    const int erow = lane >> 2;
    const int ecol = (lane & 3) * 2;
#pragma unroll
    for (int mf = 0; mf < 4; ++mf) {
#pragma unroll
        for (int nf = 0; nf < 4; ++nf) {
            const int r0 = m0 + wm + mf * 16 + erow;
            const int cc = n0 + wn + nf * 8 + ecol;
            const float2 bv = *reinterpret_cast<const float2*>(&g_merged_b[cc]);
            float2 v0 = make_float2(acc[mf][nf][0] + bv.x, acc[mf][nf][1] + bv.y);
            float2 v1 = make_float2(acc[mf][nf][2] + bv.x, acc[mf][nf][3] + bv.y);
            *reinterpret_cast<float2*>(out + (size_t)r0 * D_ + cc) = v0;
            *reinterpret_cast<float2*>(out + (size_t)(r0 + 8) * D_ + cc) = v1;
        }
    }
}

// ---------------- launch ----------------------------------------------------
extern "C" void kernel_launch(void* const* d_in, const int* in_sizes, int n_in,
                              void* d_out, int out_size) {
    const float* x  = (const float*)d_in[0];
    const float* rw = (const float*)d_in[1];
    const float* rb = (const float*)d_in[2];
    const float* ew = (const float*)d_in[3];
    const float* eb = (const float*)d_in[4];
    float* out = (float*)d_out;
    (void)in_sizes; (void)n_in; (void)out_size;

    cudaFuncSetAttribute(gemm_kernel,
                         cudaFuncAttributeMaxDynamicSharedMemorySize, SMEM_TOTAL);

    pool_partial_kernel<<<dim3(D_ / 256, B_, NCH), 256>>>(x);
    pool_final_kernel<<<dim3(D_ / 256, B_), 256>>>();
    router_kernel<<<1, 1024>>>(rw, rb);
    merge_kernel<<<(D_ * D_ / 4) / 256, 256>>>(ew, eb);
    split_x_kernel<<<(M_ * D_ / 4) / 256, 256>>>(x);
    gemm_kernel<<<dim3(D_ / BN, M_ / BM), 256, SMEM_TOTAL>>>(out);
}